// round 8
// baseline (speedup 1.0000x reference)
#include <cuda_runtime.h>
#include <math.h>

// Problem-fixed shapes
#define H   4096
#define W   4096
#define W2  8192

#define SCONST       1e-12f
#define EPS_V_FLOOR  (1e-32f / 6.0f)
#define PI_D         (3.14159265358979323846f / 1.1f)
#define PI_2         1.57079632679489662f

#define JB   256                 // columns per block (one thread per column)
#define RPB  64                  // rows per block strip
#define NBX  (W / JB)            // 16
#define NBY  (H / RPB)           // 64
#define NPART (NBX * NBY)        // 1024

__device__ double g_partials[NPART];

// ---------------------------------------------------------------------------
// Shared math tail: from derivatives to the penalty value.
// ---------------------------------------------------------------------------
__device__ __forceinline__ float penalty_val(float ex, float ey,
                                             float exx, float exy, float eyy,
                                             float c) {
    const float exs = ex + SCONST;
    const float eys = ey + SCONST;
    const float x2 = exs * exs;
    const float y2 = eys * eys;
    const float ev2 = x2 + y2;
    const float rinv = rsqrtf(ev2);                  // MUFU.RSQ
    const float ev = fmaxf(ev2 * rinv, EPS_V_FLOOR);
    float num = fmaf(y2, exx, x2 * eyy);
    num = fmaf(-2.0f * (exs * eys), exy, num);
    const float rinv3 = (rinv * rinv) * rinv;
    const float kabs = fabsf(num) * rinv3;

    // |atan(ev/c)| = atan(ev/|c|); reflect about pi/2 so poly arg is in [0,1].
    const float ac = fabsf(c);
    const float z = __fdividef(fminf(ev, ac), fmaxf(ev, ac));
    const float w = z * z;
    // A&S 4.4.49 degree-15 odd minimax, |err| < 2e-8 on [0,1]
    float p = fmaf(w, -0.0040540580f, 0.0218612288f);
    p = fmaf(w, p, -0.0559098861f);
    p = fmaf(w, p, 0.0964200441f);
    p = fmaf(w, p, -0.1390853351f);
    p = fmaf(w, p, 0.1994653599f);
    p = fmaf(w, p, -0.3332985605f);
    p = fmaf(w, p, 0.9999993329f);
    float t = z * p;
    t = (ev > ac) ? (PI_2 - t) : t;

    // fmaxf(NaN, 0) = 0 reproduces nansum dropping NaNs
    return fmaxf(fmaf(kabs, t, -PI_D), 0.0f);
}

// ---------------------------------------------------------------------------
// Generic (boundary-exact) path. Mirrors the reference's composed one-sided
// operators on the column-mirrored [H, 2W] field. Cold: <0.2% of elements.
// ---------------------------------------------------------------------------
__device__ __forceinline__ float Mld(const float* __restrict__ e, int i, int g) {
    int j = g < W ? g : (W2 - 1 - g);
    return __ldg(e + i * W + j);
}

__device__ __noinline__ float generic_val(const float* __restrict__ e,
                                          int i, int j, float d) {
    const float rd = 1.0f / d;
    const float r2d = 0.5f / d;

    auto EXg = [&](int ii, int g) -> float {
        if (ii == 0)     return (Mld(e, 1, g) - Mld(e, 0, g)) * rd;
        if (ii == H - 1) return (Mld(e, H - 1, g) - Mld(e, H - 2, g)) * rd;
        return (Mld(e, ii + 1, g) - Mld(e, ii - 1, g)) * r2d;
    };
    auto EYg = [&](int ii, int g) -> float {
        if (g == 0) return (Mld(e, ii, 1) - Mld(e, ii, 0)) * rd;
        return (Mld(e, ii, g + 1) - Mld(e, ii, g - 1)) * r2d;  // g+1 <= W+1, mapped
    };

    const float ex = EXg(i, j);
    const float ey = EYg(i, j);
    float exx, exy, eyy;
    if (i == 0)
        exx = (EXg(1, j) - EXg(0, j)) * rd;
    else if (i == H - 1)
        exx = (EXg(H - 1, j) - EXg(H - 2, j)) * rd;
    else
        exx = (EXg(i + 1, j) - EXg(i - 1, j)) * r2d;
    if (j == 0) {
        exy = (EXg(i, 1) - EXg(i, 0)) * rd;
        eyy = (EYg(i, 1) - EYg(i, 0)) * rd;
    } else {
        exy = (EXg(i, j + 1) - EXg(i, j - 1)) * r2d;
        eyy = (EYg(i, j + 1) - EYg(i, j - 1)) * r2d;
    }
    const float c = __ldg(e + i * W + j);
    return penalty_val(ex, ey, exx, exy, eyy, c);
}

__device__ __forceinline__ float warp_reduce_f(float v) {
#pragma unroll
    for (int o = 16; o > 0; o >>= 1)
        v += __shfl_xor_sync(0xffffffffu, v, o);
    return v;
}

// ---------------------------------------------------------------------------
// Main kernel: one thread per column, 64 rows per thread in 4-row
// straight-line super-iterations. No shared tile, no syncthreads in the loop.
// ---------------------------------------------------------------------------
__global__ __launch_bounds__(256, 4)
void curve_kernel(const float* __restrict__ eps, const float* __restrict__ gs) {
    __shared__ double warp_part[8];

    const float d = *gs;
    const float r2d = 0.5f / d;
    const float r2d2 = r2d * r2d;

    const int tid = threadIdx.x;
    const int j = blockIdx.x * JB + tid;
    const int i0 = blockIdx.y * RPB;
    const bool jfast = (j >= 2) & (j <= W - 3);

    const float* p = eps + (long)i0 * W + j;   // points at (t, j)
    float acc = 0.0f;

    for (int t = i0; t < i0 + RPB; t += 4) {
        const bool rows_ok = (t >= 2) & (t <= H - 6);
        if (rows_ok & jfast) {
            // 28 coalesced loads with compile-time immediate offsets
            float cC[8], cL[6], cR[6], cL2[4], cR2[4];
#pragma unroll
            for (int r = 0; r < 8; r++) cC[r] = __ldg(p + (r - 2) * W);
#pragma unroll
            for (int r = 0; r < 6; r++) {
                cL[r] = __ldg(p + (r - 1) * W - 1);
                cR[r] = __ldg(p + (r - 1) * W + 1);
            }
#pragma unroll
            for (int r = 0; r < 4; r++) {
                cL2[r] = __ldg(p + r * W - 2);
                cR2[r] = __ldg(p + r * W + 2);
            }
#pragma unroll
            for (int q = 0; q < 4; q++) {
                const float c = cC[q + 2];
                const float ex = (cC[q + 3] - cC[q + 1]) * r2d;
                const float ey = (cR[q + 1] - cL[q + 1]) * r2d;
                const float exx = (cC[q + 4] + cC[q] - 2.0f * c) * r2d2;
                const float eyy = (cR2[q] + cL2[q] - 2.0f * c) * r2d2;
                const float exy = ((cR[q + 2] - cR[q]) - (cL[q + 2] - cL[q])) * r2d2;
                acc += penalty_val(ex, ey, exx, exy, eyy, c);
            }
        } else {
#pragma unroll
            for (int q = 0; q < 4; q++)
                acc += generic_val(eps, t + q, j, d);
        }
        p += 4 * W;
    }

    const float wsum = warp_reduce_f(acc);
    if ((tid & 31) == 0) warp_part[tid >> 5] = (double)wsum;
    __syncthreads();
    if (tid == 0) {
        double s = 0.0;
#pragma unroll
        for (int w = 0; w < 8; w++) s += warp_part[w];
        g_partials[blockIdx.y * NBX + blockIdx.x] = s;
    }
}

__global__ __launch_bounds__(256)
void reduce_kernel(float* __restrict__ out, const float* __restrict__ gs) {
    __shared__ double sm[256];
    const int t = threadIdx.x;
    // 1024 partials: 4 independent loads per thread
    double s = g_partials[t] + g_partials[t + 256] +
               g_partials[t + 512] + g_partials[t + 768];
    sm[t] = s;
    __syncthreads();
    for (int off = 128; off > 0; off >>= 1) {
        if (t < off) sm[t] += sm[t + off];
        __syncthreads();
    }
    if (t == 0) {
        const float d = *gs;
        // x2: mirror-symmetric halves contribute identically; ALPHA = 1
        out[0] = (float)(sm[0] * 2.0 * (double)d * (double)d);
    }
}

extern "C" void kernel_launch(void* const* d_in, const int* in_sizes, int n_in,
                              void* d_out, int out_size) {
    const float* eps = (const float*)d_in[0];
    const float* gs  = (const float*)d_in[1];
    float* out = (float*)d_out;

    dim3 grid(NBX, NBY);   // 16 x 64 = 1024 blocks
    dim3 block(256);
    curve_kernel<<<grid, block>>>(eps, gs);
    reduce_kernel<<<1, 256>>>(out, gs);
}